// round 9
// baseline (speedup 1.0000x reference)
#include <cuda_runtime.h>
#include <mma.h>
#include <cstdint>

using namespace nvcuda;

#define N_NODES 50000
#define D_IN    128
#define D_OUT   64

// h scratch: h[row][c] = g_h4[row*16 + c/4]
__device__ float4 g_h4[N_NODES * (D_OUT / 4)];

// ---------------------------------------------------------------------------
// Kernel 1: h = x @ W via tf32 mma.sync, both operands staged in smem.
//   xs: [128][132] tf32 (A, row-major, ld=132 -> lane t hits bank t)
//   wt: [64][132]  tf32 (B=W^T, col-major frag ld=132 -> lane t hits bank t)
// Block: 256 thr / 8 warps, 128 rows; warp w owns rows [16w,16w+16) x 64 cols.
// ---------------------------------------------------------------------------
#define XS_LD 132
#define WT_LD 132
#define SMEM_WT_OFF (128 * XS_LD)                       // floats
#define GEMM_SMEM   ((128 * XS_LD + 64 * WT_LD) * 4)    // 101376 B

__global__ __launch_bounds__(256) void gemm_tc_kernel(
    const float* __restrict__ x,
    const float* __restrict__ w,
    float* __restrict__ h,
    int n_nodes)
{
    extern __shared__ float sm[];
    float* xs = sm;                  // [128][XS_LD]
    float* wt = sm + SMEM_WT_OFF;    // [64][WT_LD], wt[n][k]

    const int tid = threadIdx.x;
    const int wid = tid >> 5;
    const int row0 = blockIdx.x * 128;

    // Stage W^T (8192 elems): coalesced gmem read, conflict-free smem scatter
    #pragma unroll
    for (int i = tid; i < D_IN * D_OUT; i += 256) {
        int k = i >> 6, n = i & 63;
        wt[n * WT_LD + k] = wmma::__float_to_tf32(w[i]);
    }
    // Stage x tile: 128 rows x 32 float4, coalesced
    {
        const float4* x4 = (const float4*)x;
        #pragma unroll
        for (int i = tid; i < 128 * 32; i += 256) {
            int r = i >> 5, c4 = i & 31;
            if (row0 + r < n_nodes) {
                float4 v = x4[(size_t)(row0 + r) * 32 + c4];
                float* p = xs + r * XS_LD + c4 * 4;
                p[0] = wmma::__float_to_tf32(v.x);
                p[1] = wmma::__float_to_tf32(v.y);
                p[2] = wmma::__float_to_tf32(v.z);
                p[3] = wmma::__float_to_tf32(v.w);
            }
        }
    }
    __syncthreads();

    const int wrow = row0 + wid * 16;
    if (wrow >= n_nodes) return;    // 50000 % 16 == 0: tiles all-or-nothing

    wmma::fragment<wmma::accumulator, 16, 16, 8, float> c[4];
    #pragma unroll
    for (int n = 0; n < 4; n++) wmma::fill_fragment(c[n], 0.0f);

    const float* a_base = xs + wid * 16 * XS_LD;

    #pragma unroll
    for (int k = 0; k < 16; k++) {
        wmma::fragment<wmma::matrix_a, 16, 16, 8, wmma::precision::tf32, wmma::row_major> a;
        wmma::load_matrix_sync(a, a_base + k * 8, XS_LD);
        #pragma unroll
        for (int n = 0; n < 4; n++) {
            wmma::fragment<wmma::matrix_b, 16, 16, 8, wmma::precision::tf32, wmma::col_major> b;
            wmma::load_matrix_sync(b, wt + (n * 16) * WT_LD + k * 8, WT_LD);
            wmma::mma_sync(c[n], a, b, c[n]);
        }
    }

    float* hp = h + (size_t)wrow * D_OUT;
    #pragma unroll
    for (int n = 0; n < 4; n++)
        wmma::store_matrix_sync(hp + n * 16, c[n], D_OUT, wmma::mem_row_major);
}

// ---------------------------------------------------------------------------
// Kernel 2: aggregation with in-block CSR bound discovery.
// Block = 256 thr = 8 warps = 8 consecutive nodes. Lanes tid<9 each binary
// search lower_bound(dst, node_base+tid) over the sorted dst array (L2
// resident); bounds shared via smem. Then warp w aggregates node w's edge
// range: lanes 0-15 even edges, 16-31 odd edges, shfl_xor(16) combine.
// No fill kernel, no atomics, no init.
// ---------------------------------------------------------------------------
__global__ __launch_bounds__(256) void agg_kernel(
    const float4* __restrict__ h4,
    const int*    __restrict__ src,
    const float*  __restrict__ val,
    const int*    __restrict__ dst,
    const float4* __restrict__ bias4,
    float4*       __restrict__ out4,
    int n_nodes, int n_edges)
{
    __shared__ int bounds[9];

    const int tid = threadIdx.x;
    const int node_base = blockIdx.x * 8;

    if (tid < 9) {
        // lower_bound: first e with dst[e] >= node_base + tid
        int target = node_base + tid;
        int lo = 0, hi = n_edges;
        while (lo < hi) {
            int mid = (lo + hi) >> 1;
            if (__ldg(&dst[mid]) < target) lo = mid + 1; else hi = mid;
        }
        bounds[tid] = lo;
    }
    __syncthreads();

    const int wid  = tid >> 5;
    const int lane = tid & 31;
    const int f4   = lane & 15;
    const int half = lane >> 4;
    const int node = node_base + wid;
    if (node >= n_nodes) return;

    const int s = bounds[wid];
    const int t = bounds[wid + 1];

    float4 acc = make_float4(0.f, 0.f, 0.f, 0.f);

    #pragma unroll 4
    for (int e = s + half; e < t; e += 2) {
        float  v  = __ldg(&val[e]);
        int    sc = __ldg(&src[e]);
        float4 hv = __ldg(&h4[(size_t)sc * 16 + f4]);
        acc.x += v * hv.x; acc.y += v * hv.y;
        acc.z += v * hv.z; acc.w += v * hv.w;
    }

    acc.x += __shfl_xor_sync(0xffffffffu, acc.x, 16);
    acc.y += __shfl_xor_sync(0xffffffffu, acc.y, 16);
    acc.z += __shfl_xor_sync(0xffffffffu, acc.z, 16);
    acc.w += __shfl_xor_sync(0xffffffffu, acc.w, 16);

    if (half == 0) {
        float4 b = __ldg(&bias4[f4]);
        acc.x += b.x; acc.y += b.y; acc.z += b.z; acc.w += b.w;
        out4[(size_t)node * 16 + f4] = acc;
    }
}

// ---------------------------------------------------------------------------
extern "C" void kernel_launch(void* const* d_in, const int* in_sizes, int n_in,
                              void* d_out, int out_size)
{
    const float* x    = (const float*)d_in[0];   // [N, 128]
    const int*   esrc = (const int*)  d_in[1];   // [E]
    const int*   edst = (const int*)  d_in[2];   // [E]
    const float* eval = (const float*)d_in[3];   // [E]
    const float* w    = (const float*)d_in[4];   // [128, 64]
    const float* bias = (const float*)d_in[5];   // [64]
    float* out = (float*)d_out;                  // [N, 64]

    const int n_nodes = in_sizes[0] / D_IN;
    const int n_edges = in_sizes[1];

    float4* h4;
    cudaGetSymbolAddress((void**)&h4, g_h4);

    // 1) h = x @ W (tf32 mma.sync, smem-staged operands)
    {
        cudaFuncSetAttribute(gemm_tc_kernel,
                             cudaFuncAttributeMaxDynamicSharedMemorySize, GEMM_SMEM);
        int blocks = (n_nodes + 127) / 128;
        gemm_tc_kernel<<<blocks, 256, GEMM_SMEM>>>(x, w, (float*)h4, n_nodes);
    }

    // 2) out = bias + A @ h (block finds its own CSR bounds; no fill kernel)
    {
        int blocks = (n_nodes + 7) / 8;
        agg_kernel<<<blocks, 256>>>(h4, esrc, eval, edst,
                                    (const float4*)bias, (float4*)out,
                                    n_nodes, n_edges);
    }
}

// round 10
// speedup vs baseline: 1.1585x; 1.1585x over previous
#include <cuda_runtime.h>
#include <mma.h>
#include <cstdint>

using namespace nvcuda;

#define N_NODES 50000
#define D_IN    128
#define D_OUT   64

// h scratch: h[row][c] = g_h4[row*16 + c/4]
__device__ float4 g_h4[N_NODES * (D_OUT / 4)];
// CSR row starts
__device__ int g_row_start[N_NODES + 1];

// ---------------------------------------------------------------------------
// Kernel 1: h = x @ W via tf32 mma.sync, both operands staged in smem.
//   xs: [128][132] tf32 (A row-major, ld=132 -> conflict-free)
//   wt: [64][132]  tf32 (B=W^T col-major frag, ld=132 -> conflict-free)
// Block: 256 thr / 8 warps, 128 rows; warp w owns rows [16w,16w+16) x 64 cols.
// ---------------------------------------------------------------------------
#define XS_LD 132
#define WT_LD 132
#define SMEM_WT_OFF (128 * XS_LD)                       // floats
#define GEMM_SMEM   ((128 * XS_LD + 64 * WT_LD) * 4)    // 101376 B

__global__ __launch_bounds__(256) void gemm_tc_kernel(
    const float* __restrict__ x,
    const float* __restrict__ w,
    float* __restrict__ h,
    int n_nodes)
{
    extern __shared__ float sm[];
    float* xs = sm;                  // [128][XS_LD]
    float* wt = sm + SMEM_WT_OFF;    // [64][WT_LD], wt[n][k]

    const int tid = threadIdx.x;
    const int wid = tid >> 5;
    const int row0 = blockIdx.x * 128;

    #pragma unroll
    for (int i = tid; i < D_IN * D_OUT; i += 256) {
        int k = i >> 6, n = i & 63;
        wt[n * WT_LD + k] = wmma::__float_to_tf32(w[i]);
    }
    {
        const float4* x4 = (const float4*)x;
        #pragma unroll
        for (int i = tid; i < 128 * 32; i += 256) {
            int r = i >> 5, c4 = i & 31;
            if (row0 + r < n_nodes) {
                float4 v = x4[(size_t)(row0 + r) * 32 + c4];
                float* p = xs + r * XS_LD + c4 * 4;
                p[0] = wmma::__float_to_tf32(v.x);
                p[1] = wmma::__float_to_tf32(v.y);
                p[2] = wmma::__float_to_tf32(v.z);
                p[3] = wmma::__float_to_tf32(v.w);
            }
        }
    }
    __syncthreads();

    const int wrow = row0 + wid * 16;
    if (wrow >= n_nodes) return;    // 50000 % 16 == 0

    wmma::fragment<wmma::accumulator, 16, 16, 8, float> c[4];
    #pragma unroll
    for (int n = 0; n < 4; n++) wmma::fill_fragment(c[n], 0.0f);

    const float* a_base = xs + wid * 16 * XS_LD;

    #pragma unroll
    for (int k = 0; k < 16; k++) {
        wmma::fragment<wmma::matrix_a, 16, 16, 8, wmma::precision::tf32, wmma::row_major> a;
        wmma::load_matrix_sync(a, a_base + k * 8, XS_LD);
        #pragma unroll
        for (int n = 0; n < 4; n++) {
            wmma::fragment<wmma::matrix_b, 16, 16, 8, wmma::precision::tf32, wmma::col_major> b;
            wmma::load_matrix_sync(b, wt + (n * 16) * WT_LD + k * 8, WT_LD);
            wmma::mma_sync(c[n], a, b, c[n]);
        }
    }

    float* hp = h + (size_t)wrow * D_OUT;
    #pragma unroll
    for (int n = 0; n < 4; n++)
        wmma::store_matrix_sync(hp + n * 16, c[n], D_OUT, wmma::mem_row_major);
}

// ---------------------------------------------------------------------------
// Kernel 2: row_start via per-node binary search over sorted dst.
// 50001 independent threads, ~17 L2-hit probes each, one wave, coalesced out.
// ---------------------------------------------------------------------------
__global__ void fill_rowstart_kernel(const int* __restrict__ dst,
                                     int* __restrict__ row_start,
                                     int n_edges, int n_nodes)
{
    int i = blockIdx.x * blockDim.x + threadIdx.x;
    if (i > n_nodes) return;
    int lo = 0, hi = n_edges;          // lower_bound(dst, i)
    while (lo < hi) {
        int mid = (lo + hi) >> 1;
        if (__ldg(&dst[mid]) < i) lo = mid + 1; else hi = mid;
    }
    row_start[i] = lo;
}

// ---------------------------------------------------------------------------
// Kernel 3: aggregation, warp per node, shfl-broadcast metadata.
// Per 32-edge chunk: lanes load (src,val) coalesced into registers; then
// halves iterate (half 0: even j, half 1: odd j), shfl-broadcasting the
// edge's (src,val) so the h-gather is the only dependent load. f4 = lane&15.
// ---------------------------------------------------------------------------
__global__ __launch_bounds__(256) void agg_kernel(
    const float4* __restrict__ h4,
    const int*    __restrict__ src,
    const float*  __restrict__ val,
    const int*    __restrict__ row_start,
    const float4* __restrict__ bias4,
    float4*       __restrict__ out4,
    int n_nodes)
{
    const int lane = threadIdx.x & 31;
    const int f4   = lane & 15;
    const int half = lane >> 4;
    const int node = (blockIdx.x * blockDim.x + threadIdx.x) >> 5;
    if (node >= n_nodes) return;

    const int s = __ldg(&row_start[node]);
    const int t = __ldg(&row_start[node + 1]);

    float4 acc = make_float4(0.f, 0.f, 0.f, 0.f);

    for (int base = s; base < t; base += 32) {
        const int cnt = min(32, t - base);
        const int e   = base + lane;
        float v  = 0.f;
        int   sc = 0;
        if (e < t) { v = __ldg(&val[e]); sc = __ldg(&src[e]); }  // coalesced

        const int iters = (cnt + 1) >> 1;
        #pragma unroll 4
        for (int jj = 0; jj < iters; jj++) {
            const int j = (jj << 1) | half;                      // <= 31
            float vj  = __shfl_sync(0xffffffffu, v,  j);
            int   scj = __shfl_sync(0xffffffffu, sc, j);
            if (j < cnt) {                                       // uniform per half
                float4 hv = __ldg(&h4[(size_t)scj * 16 + f4]);
                acc.x += vj * hv.x; acc.y += vj * hv.y;
                acc.z += vj * hv.z; acc.w += vj * hv.w;
            }
        }
    }

    acc.x += __shfl_xor_sync(0xffffffffu, acc.x, 16);
    acc.y += __shfl_xor_sync(0xffffffffu, acc.y, 16);
    acc.z += __shfl_xor_sync(0xffffffffu, acc.z, 16);
    acc.w += __shfl_xor_sync(0xffffffffu, acc.w, 16);

    if (half == 0) {
        float4 b = __ldg(&bias4[f4]);
        acc.x += b.x; acc.y += b.y; acc.z += b.z; acc.w += b.w;
        out4[(size_t)node * 16 + f4] = acc;
    }
}

// ---------------------------------------------------------------------------
extern "C" void kernel_launch(void* const* d_in, const int* in_sizes, int n_in,
                              void* d_out, int out_size)
{
    const float* x    = (const float*)d_in[0];   // [N, 128]
    const int*   esrc = (const int*)  d_in[1];   // [E]
    const int*   edst = (const int*)  d_in[2];   // [E]
    const float* eval = (const float*)d_in[3];   // [E]
    const float* w    = (const float*)d_in[4];   // [128, 64]
    const float* bias = (const float*)d_in[5];   // [64]
    float* out = (float*)d_out;                  // [N, 64]

    const int n_nodes = in_sizes[0] / D_IN;
    const int n_edges = in_sizes[1];

    float4* h4;
    cudaGetSymbolAddress((void**)&h4, g_h4);
    int* row_start;
    cudaGetSymbolAddress((void**)&row_start, g_row_start);

    // 1) row_start by parallel binary search (one wave, independent threads)
    fill_rowstart_kernel<<<(n_nodes + 1 + 255) / 256, 256>>>(edst, row_start, n_edges, n_nodes);

    // 2) h = x @ W (tf32 mma.sync)
    {
        cudaFuncSetAttribute(gemm_tc_kernel,
                             cudaFuncAttributeMaxDynamicSharedMemorySize, GEMM_SMEM);
        int blocks = (n_nodes + 127) / 128;
        gemm_tc_kernel<<<blocks, 256, GEMM_SMEM>>>(x, w, (float*)h4, n_nodes);
    }

    // 3) out = bias + A @ h (warp per node, shfl-broadcast metadata)
    {
        size_t threads = (size_t)n_nodes * 32;
        agg_kernel<<<(unsigned)((threads + 255) / 256), 256>>>(
            h4, esrc, eval, row_start, (const float4*)bias, (float4*)out, n_nodes);
    }
}